// round 12
// baseline (speedup 1.0000x reference)
#include <cuda_runtime.h>
#include <cstdint>
#include <cstddef>

#define T_TOK 2048
#define LM    4096
#define VIS   32768
#define FF    1024
#define NB    16
#define VKC   128                 // vision: K elements per chunk
#define NVCH  (VIS / VKC)         // 256 chunks

// ---------------- scratch (device globals; no allocations allowed) ----------
__device__ float g_yv_part[NVCH][NB][FF];   // 16 MB vision split-K partials
__device__ float g_yv[NB][FF];              // vision projection [16,1024]
__device__ float g_part[2][T_TOK][FF];      // 16 MB GEMM split-K partials
__device__ float g_a0[T_TOK][LM];           // 32 MB tf32-rounded grd_hidden
__device__ float g_h0[T_TOK][FF];           // ping (tf32-rounded activations)
__device__ float g_h1[T_TOK][FF];           // pong
__device__ float g_w1[LM * FF];             // 16 MB tf32-rounded W1_lang
__device__ float g_w2[FF * FF];             // 4 MB tf32-rounded W2
__device__ float g_w3[FF * FF];
__device__ float g_w4[FF * FF];
__device__ int   g_tbi[T_TOK];              // normalized token_batch_idx

__device__ __forceinline__ uint32_t to_tf32(float x) {
    uint32_t y;
    asm("cvt.rna.tf32.f32 %0, %1;" : "=r"(y) : "f"(x));
    return y;
}
__device__ __forceinline__ uint32_t smem_u32(const void* p) {
    uint32_t a;
    asm("{ .reg .u64 t; cvta.to.shared.u64 t, %1; cvt.u32.u64 %0, t; }"
        : "=r"(a) : "l"(p));
    return a;
}

// ---------------- idx dtype resolve (int64 vs int32, decided on-device) -----
__global__ void resolve_idx_kernel(const int* __restrict__ raw) {
    __shared__ int red[32];
    __shared__ int is64;
    int tid = threadIdx.x;
    int local = raw[2 * tid + 1];
    #pragma unroll
    for (int o = 16; o; o >>= 1) local += __shfl_down_sync(~0u, local, o);
    if ((tid & 31) == 0) red[tid >> 5] = local;
    __syncthreads();
    if (tid == 0) {
        int s = 0;
        for (int w = 0; w < 32; w++) s += red[w];
        is64 = (s == 0);
    }
    __syncthreads();
    int f = is64;
    for (int i = tid; i < T_TOK; i += 1024)
        g_tbi[i] = f ? raw[2 * i] : raw[i];
}

// ---------------- rounding copy: dst[i] = rna_tf32(src[i]) ------------------
__global__ void __launch_bounds__(256) round_copy(
    const float* __restrict__ src, float* __restrict__ dst) {
    int i = blockIdx.x * 256 + threadIdx.x;   // float4 index
    float4 v = *(const float4*)(src + (size_t)i * 4);
    float4 r;
    r.x = __uint_as_float(to_tf32(v.x));
    r.y = __uint_as_float(to_tf32(v.y));
    r.z = __uint_as_float(to_tf32(v.z));
    r.w = __uint_as_float(to_tf32(v.w));
    *(float4*)(dst + (size_t)i * 4) = r;
}

// ---------------- vision GEMM: yv[16,1024] = vis_flat[16,32768] @ W1_vis ----
__global__ void __launch_bounds__(256) vis_gemm_partial(
    const float* __restrict__ vis, const float* __restrict__ W1) {
    const int kc = blockIdx.x;             // 0..255
    const int k0 = kc * VKC;
    const int tid = threadIdx.x;
    __shared__ float vs[NB][VKC];          // 8 KB
    for (int i = tid; i < NB * (VKC / 4); i += 256) {
        int b = i / (VKC / 4), q = i % (VKC / 4);
        *(float4*)&vs[b][q * 4] =
            *(const float4*)&vis[(size_t)b * VIS + k0 + q * 4];
    }
    __syncthreads();

    float4 acc[NB];
    #pragma unroll
    for (int b = 0; b < NB; b++) acc[b] = make_float4(0.f, 0.f, 0.f, 0.f);

    const float* Wp = W1 + (size_t)k0 * FF + tid * 4;
    #pragma unroll 2
    for (int k = 0; k < VKC; k += 2) {
        float4 w0 = *(const float4*)(Wp + (size_t)k * FF);
        float4 w1 = *(const float4*)(Wp + (size_t)(k + 1) * FF);
        #pragma unroll
        for (int b = 0; b < NB; b++) {
            float v0 = vs[b][k], v1 = vs[b][k + 1];
            acc[b].x = fmaf(v0, w0.x, acc[b].x);
            acc[b].y = fmaf(v0, w0.y, acc[b].y);
            acc[b].z = fmaf(v0, w0.z, acc[b].z);
            acc[b].w = fmaf(v0, w0.w, acc[b].w);
            acc[b].x = fmaf(v1, w1.x, acc[b].x);
            acc[b].y = fmaf(v1, w1.y, acc[b].y);
            acc[b].z = fmaf(v1, w1.z, acc[b].z);
            acc[b].w = fmaf(v1, w1.w, acc[b].w);
        }
    }
    #pragma unroll
    for (int b = 0; b < NB; b++)
        *(float4*)&g_yv_part[kc][b][tid * 4] = acc[b];
}

// 4 threads per (b,n) output, shfl combine; 256 blocks x 256 threads
__global__ void __launch_bounds__(256) vis_reduce() {
    int p = blockIdx.x * 64 + (threadIdx.x >> 2);   // pair 0..16383
    int q = threadIdx.x & 3;
    int b = p >> 10, n = p & 1023;
    float s = 0.f;
    const int c0 = q * (NVCH / 4);
    #pragma unroll 8
    for (int c = 0; c < NVCH / 4; c++) s += g_yv_part[c0 + c][b][n];
    s += __shfl_xor_sync(~0u, s, 1);
    s += __shfl_xor_sync(~0u, s, 2);
    if (q == 0) g_yv[b][n] = s;
}

// ---------------- main GEMM (split-K=2): part[z] = A[:,zK/2:(z+1)K/2] @ Bw
// tf32 mma.sync m16n8k8. CTA 128x128, 256 thr = 8 warps (2m x 4n), warp tile
// 64x32. K-tile 32. BOTH operands pre-rounded tf32 in gmem -> pure cp.async
// mainloop (no LDG/STS), 2-stage pipeline. Dynamic smem 71680 B.
__global__ void __launch_bounds__(256, 2) mlp_gemm(
    const float* __restrict__ A, const float* __restrict__ Bw,
    float* __restrict__ part, int Kfull) {
    extern __shared__ float smem[];
    // layout (floats): A0[128*36] A1[128*36] B0[32*136] B1[32*136]
    const uint32_t s_u32   = smem_u32(smem);
    const uint32_t A_STAGE = 128 * 36 * 4;   // 18432 B
    const uint32_t B_BASE  = 2 * A_STAGE;    // 36864
    const uint32_t B_STAGE = 32 * 136 * 4;   // 17408 B

    const int tid  = threadIdx.x;
    const int m0   = blockIdx.y * 128, n0 = blockIdx.x * 128;
    const int z    = blockIdx.z;
    const int Keff = Kfull >> 1;
    const int koff = z * Keff;
    const int warp = tid >> 5, lane = tid & 31;
    const int wm   = warp >> 2, wn = warp & 3;   // 2m x 4n
    const int g    = lane >> 2, tq = lane & 3;

    float acc[4][4][4];
    #pragma unroll
    for (int mi = 0; mi < 4; mi++)
        #pragma unroll
        for (int ni = 0; ni < 4; ni++)
            #pragma unroll
            for (int q = 0; q < 4; q++) acc[mi][ni][q] = 0.f;

    // cp.async segment maps (4 x 16B per thread for each of A and B)
    // A tile: 128 rows x 32 floats (8 segs/row). seg s: row s>>3, off (s&7)*16B
    // B tile: 32 rows x 128 floats (32 segs/row). seg s: row s>>5, off (s&31)*16B
    const float* Abase = A + (size_t)m0 * Kfull + koff;
    const float* Bbase = Bw + (size_t)koff * FF + n0;

    auto issue = [&](int kt, int buf) {
        const int kk0 = kt * 32;
        #pragma unroll
        for (int i = 0; i < 4; i++) {
            int s = tid + i * 256;
            int ar = s >> 3, ao = s & 7;
            uint32_t adst = s_u32 + (uint32_t)buf * A_STAGE +
                            (uint32_t)(ar * 144 + ao * 16);
            const float* asrc = Abase + (size_t)ar * Kfull + kk0 + ao * 4;
            asm volatile("cp.async.cg.shared.global [%0], [%1], 16;"
                         :: "r"(adst), "l"(asrc) : "memory");
            int br = s >> 5, bo = s & 31;
            uint32_t bdst = s_u32 + B_BASE + (uint32_t)buf * B_STAGE +
                            (uint32_t)(br * 544 + bo * 16);
            const float* bsrc = Bbase + (size_t)(kk0 + br) * FF + bo * 4;
            asm volatile("cp.async.cg.shared.global [%0], [%1], 16;"
                         :: "r"(bdst), "l"(bsrc) : "memory");
        }
        asm volatile("cp.async.commit_group;" ::: "memory");
    };

    const uint32_t a_frag_off =
        (uint32_t)((lane & 15) * 144 + (lane >> 4) * 16);
    const int KT = Keff >> 5;

    issue(0, 0);
    #pragma unroll 1
    for (int kt = 0; kt < KT; kt++) {
        const int cur = kt & 1;
        if (kt + 1 < KT) {
            issue(kt + 1, cur ^ 1);
            asm volatile("cp.async.wait_group 1;" ::: "memory");
        } else {
            asm volatile("cp.async.wait_group 0;" ::: "memory");
        }
        __syncthreads();

        const uint32_t as_cur = s_u32 + (uint32_t)cur * A_STAGE;
        const float* Bsf = smem + (B_BASE >> 2) + cur * (B_STAGE >> 2);
        #pragma unroll
        for (int kk = 0; kk < 32; kk += 8) {
            uint32_t af[4][4];
            #pragma unroll
            for (int mi = 0; mi < 4; mi++) {
                uint32_t addr = as_cur +
                    (uint32_t)((wm * 64 + mi * 16) * 144 + kk * 4) + a_frag_off;
                asm volatile(
                    "ldmatrix.sync.aligned.m8n8.x4.shared.b16 {%0,%1,%2,%3}, [%4];"
                    : "=r"(af[mi][0]), "=r"(af[mi][1]),
                      "=r"(af[mi][2]), "=r"(af[mi][3])
                    : "r"(addr));
            }
            uint32_t bf[4][2];
            #pragma unroll
            for (int ni = 0; ni < 4; ni++) {
                int c = wn * 32 + ni * 8 + g;
                bf[ni][0] = __float_as_uint(Bsf[(kk + tq) * 136 + c]);
                bf[ni][1] = __float_as_uint(Bsf[(kk + tq + 4) * 136 + c]);
            }
            #pragma unroll
            for (int mi = 0; mi < 4; mi++)
                #pragma unroll
                for (int ni = 0; ni < 4; ni++)
                    asm volatile(
                        "mma.sync.aligned.m16n8k8.row.col.f32.tf32.tf32.f32 "
                        "{%0,%1,%2,%3}, {%4,%5,%6,%7}, {%8,%9}, {%0,%1,%2,%3};"
                        : "+f"(acc[mi][ni][0]), "+f"(acc[mi][ni][1]),
                          "+f"(acc[mi][ni][2]), "+f"(acc[mi][ni][3])
                        : "r"(af[mi][0]), "r"(af[mi][1]), "r"(af[mi][2]),
                          "r"(af[mi][3]), "r"(bf[ni][0]), "r"(bf[ni][1]));
        }
        __syncthreads();   // compute done before buffer rewritten next iter
    }

    // epilogue: raw partial store
    float* P = part + (size_t)z * T_TOK * FF;
    #pragma unroll
    for (int mi = 0; mi < 4; mi++) {
        int r0 = m0 + wm * 64 + mi * 16 + g;
        #pragma unroll
        for (int rr = 0; rr < 2; rr++) {
            int row = r0 + rr * 8;
            #pragma unroll
            for (int ni = 0; ni < 4; ni++) {
                int col = n0 + wn * 32 + ni * 8 + tq * 2;
                float2 v;
                v.x = acc[mi][ni][rr * 2 + 0];
                v.y = acc[mi][ni][rr * 2 + 1];
                *(float2*)&P[(size_t)row * FF + col] = v;
            }
        }
    }
}

// -------- reduce: out = tf32(relu(p0 + p1 + bias (+ yv[tbi[row]]))) ---------
__global__ void __launch_bounds__(256) reduce_fuse(
    const float* __restrict__ bias, float* __restrict__ out, int add_vis) {
    int i   = blockIdx.x * 256 + threadIdx.x;   // float4 index
    int row = i >> 8;                           // 256 float4 per row
    int c4  = i & 255;
    float4 p0 = *(const float4*)&g_part[0][row][c4 * 4];
    float4 p1 = *(const float4*)&g_part[1][row][c4 * 4];
    float4 b  = *(const float4*)&bias[c4 * 4];
    float4 v;
    v.x = p0.x + p1.x + b.x;
    v.y = p0.y + p1.y + b.y;
    v.z = p0.z + p1.z + b.z;
    v.w = p0.w + p1.w + b.w;
    if (add_vis) {
        float4 y = *(const float4*)&g_yv[g_tbi[row]][c4 * 4];
        v.x += y.x; v.y += y.y; v.z += y.z; v.w += y.w;
    }
    float4 r;
    r.x = __uint_as_float(to_tf32(fmaxf(v.x, 0.f)));
    r.y = __uint_as_float(to_tf32(fmaxf(v.y, 0.f)));
    r.z = __uint_as_float(to_tf32(fmaxf(v.z, 0.f)));
    r.w = __uint_as_float(to_tf32(fmaxf(v.w, 0.f)));
    *(float4*)&out[(size_t)row * FF + c4 * 4] = r;
}

// ---------------- head: out[2048,6] = h4 @ W5 + b5 (warp per token) ---------
__global__ void __launch_bounds__(256) head_kernel(
    const float* __restrict__ H, const float* __restrict__ W5,
    const float* __restrict__ b5, float* __restrict__ out) {
    int t    = blockIdx.x * 8 + (threadIdx.x >> 5);
    int lane = threadIdx.x & 31;
    float a0 = 0, a1 = 0, a2 = 0, a3 = 0, a4 = 0, a5 = 0;
    const float* h = H + (size_t)t * FF;
    for (int k = lane; k < FF; k += 32) {
        float hv = h[k];
        const float2 w01 = *(const float2*)&W5[(size_t)k * 6 + 0];
        const float2 w23 = *(const float2*)&W5[(size_t)k * 6 + 2];
        const float2 w45 = *(const float2*)&W5[(size_t)k * 6 + 4];
        a0 = fmaf(hv, w01.x, a0);
        a1 = fmaf(hv, w01.y, a1);
        a2 = fmaf(hv, w23.x, a2);
        a3 = fmaf(hv, w23.y, a3);
        a4 = fmaf(hv, w45.x, a4);
        a5 = fmaf(hv, w45.y, a5);
    }
    #pragma unroll
    for (int o = 16; o; o >>= 1) {
        a0 += __shfl_down_sync(~0u, a0, o);
        a1 += __shfl_down_sync(~0u, a1, o);
        a2 += __shfl_down_sync(~0u, a2, o);
        a3 += __shfl_down_sync(~0u, a3, o);
        a4 += __shfl_down_sync(~0u, a4, o);
        a5 += __shfl_down_sync(~0u, a5, o);
    }
    if (lane == 0) {
        float* o = out + (size_t)t * 6;
        o[0] = a0 + b5[0];
        o[1] = a1 + b5[1];
        o[2] = a2 + b5[2];
        o[3] = a3 + b5[3];
        o[4] = a4 + b5[4];
        o[5] = a5 + b5[5];
    }
}

// ---------------- launch -----------------------------------------------------
extern "C" void kernel_launch(void* const* d_in, const int* in_sizes, int n_in,
                              void* d_out, int out_size) {
    const float* grd     = (const float*)d_in[0];
    const float* vis     = (const float*)d_in[1];
    const int*   tbi_raw = (const int*)d_in[2];
    const float* W1 = (const float*)d_in[3];
    const float* b1 = (const float*)d_in[4];
    const float* W2 = (const float*)d_in[5];
    const float* b2 = (const float*)d_in[6];
    const float* W3 = (const float*)d_in[7];
    const float* b3 = (const float*)d_in[8];
    const float* W4 = (const float*)d_in[9];
    const float* b4 = (const float*)d_in[10];
    const float* W5 = (const float*)d_in[11];
    const float* b5 = (const float*)d_in[12];
    float* out = (float*)d_out;

    float *h0, *h1, *part, *a0, *w1, *w2, *w3, *w4;
    cudaGetSymbolAddress((void**)&h0, g_h0);
    cudaGetSymbolAddress((void**)&h1, g_h1);
    cudaGetSymbolAddress((void**)&part, g_part);
    cudaGetSymbolAddress((void**)&a0, g_a0);
    cudaGetSymbolAddress((void**)&w1, g_w1);
    cudaGetSymbolAddress((void**)&w2, g_w2);
    cudaGetSymbolAddress((void**)&w3, g_w3);
    cudaGetSymbolAddress((void**)&w4, g_w4);

    const int SMEM = 71680;
    cudaFuncSetAttribute(mlp_gemm,
                         cudaFuncAttributeMaxDynamicSharedMemorySize, SMEM);

    const dim3 gg(8, 16, 2);   // split-K=2 -> 256 CTAs (2/SM, one wave)
    const int RB = T_TOK * FF / (256 * 4);  // reduce blocks = 2048

    resolve_idx_kernel<<<1, 1024>>>(tbi_raw);
    // round inputs + weights to tf32 (once per launch)
    round_copy<<<T_TOK * LM / 1024, 256>>>(grd, a0);
    round_copy<<<LM * FF / 1024, 256>>>(W1 + (size_t)VIS * FF, w1);
    round_copy<<<FF * FF / 1024, 256>>>(W2, w2);
    round_copy<<<FF * FF / 1024, 256>>>(W3, w3);
    round_copy<<<FF * FF / 1024, 256>>>(W4, w4);

    vis_gemm_partial<<<NVCH, 256>>>(vis, W1);
    vis_reduce<<<256, 256>>>();

    mlp_gemm<<<gg, 256, SMEM>>>(a0, w1, part, LM);
    reduce_fuse<<<RB, 256>>>(b1, h0, 1);
    mlp_gemm<<<gg, 256, SMEM>>>(h0, w2, part, FF);
    reduce_fuse<<<RB, 256>>>(b2, h1, 0);
    mlp_gemm<<<gg, 256, SMEM>>>(h1, w3, part, FF);
    reduce_fuse<<<RB, 256>>>(b3, h0, 0);
    mlp_gemm<<<gg, 256, SMEM>>>(h0, w4, part, FF);
    reduce_fuse<<<RB, 256>>>(b4, h1, 0);
    head_kernel<<<256, 256>>>(h1, W5, b5, out);
}